// round 15
// baseline (speedup 1.0000x reference)
#include <cuda_runtime.h>
#include <cuda_fp16.h>
#include <cstdint>

#define NN 100000
#define NE 1600000
#define FD 128
#define NG 64
#define NC 32

#define NBLK ((NN + 255) / 256)        // 391 scan blocks
#define NEPAD (NE + 8 * NN)            // padded edge capacity

// ---------------- scratch (static device globals; allocation-free) ----------
// g_deg zero at start (static init; re-zeroed by k_cleanup). g_scanv re-zeroed
// by k_deg_x2h before every k_scan (same-stream ordering), replay-safe.
__device__ int    g_deg[NN];
__device__ int    g_offs[NN + 1];
__device__ int    g_cursor[NN];
__device__ float2 g_edge[NEPAD];       // (.x = bitcast(src*FD), .y = weight)
__device__ float  g_dinv[NN];
__device__ int    g_scanv[NBLK];
__device__ __half g_xh[(size_t)NN * FD];      // fp16 X
__device__ __half g_aggh[(size_t)NN * FD];    // agg1 out / gemm2 out (reused)
__device__ __half g_h1h[(size_t)NN * FD];     // gemm1 out (relu'd h1)
__device__ float  g_bufB[(size_t)NN * FD];    // agg2 out fp32
__device__ float  g_pooled[NG * FD];

// ---------------- helpers -----------------------------------------------------
__device__ __forceinline__ void mma_f16(float* d, const uint32_t* a, uint32_t b0, uint32_t b1) {
    asm volatile("mma.sync.aligned.m16n8k16.row.col.f32.f16.f16.f32 "
                 "{%0,%1,%2,%3}, {%4,%5,%6,%7}, {%8,%9}, {%0,%1,%2,%3};"
                 : "+f"(d[0]), "+f"(d[1]), "+f"(d[2]), "+f"(d[3])
                 : "r"(a[0]), "r"(a[1]), "r"(a[2]), "r"(a[3]), "r"(b0), "r"(b1));
}

__device__ __forceinline__ void cp_async16(uint32_t saddr, const void* gptr, int src_bytes) {
    asm volatile("cp.async.ca.shared.global [%0], [%1], 16, %2;"
                 :: "r"(saddr), "l"(gptr), "r"(src_bytes));
}

// ---------------- deg histogram + x->fp16 + scan-flag reset --------------------
__global__ void k_deg_x2h(const int* __restrict__ dst, int ne,
                          const float* __restrict__ x) {
    int gid = blockIdx.x * blockDim.x + threadIdx.x;
    int stride = gridDim.x * blockDim.x;
    if (gid < ne) atomicAdd(&g_deg[dst[gid]], 1);
    if (gid < NBLK) g_scanv[gid] = 0;
    for (int i = gid; i < NN * FD / 2; i += stride) {
        float2 v = ((const float2*)x)[i];
        ((__half2*)g_xh)[i] = __float22half2_rn(v);
    }
}

// ---------------- single-kernel scan over PADDED degrees + pad fill ------------
__global__ void k_scan() {
    __shared__ int warp_sums[8];
    __shared__ int red[8];
    __shared__ int s_prefix;
    int tid = threadIdx.x, bid = blockIdx.x;
    int i = bid * 256 + tid;
    int v  = (i < NN) ? g_deg[i] : 0;
    int vp = (v + 7) & ~7;                 // padded degree

    int x = vp;
    #pragma unroll
    for (int d = 1; d < 32; d <<= 1) {
        int y = __shfl_up_sync(0xffffffffu, x, d);
        if ((tid & 31) >= d) x += y;
    }
    if ((tid & 31) == 31) warp_sums[tid >> 5] = x;
    __syncthreads();
    if (tid < 8) {
        int y = warp_sums[tid];
        #pragma unroll
        for (int d = 1; d < 8; d <<= 1) {
            int z = __shfl_up_sync(0xffu, y, d);
            if (tid >= d) y += z;
        }
        warp_sums[tid] = y;
    }
    __syncthreads();
    int incl = x + ((tid >= 32) ? warp_sums[(tid >> 5) - 1] : 0);

    if (tid == 255) atomicExch(&g_scanv[bid], incl + 1);   // publish (+1 sentinel)

    int p = 0;
    for (int j = tid; j < bid; j += 256) {
        int val;
        do { val = atomicAdd(&g_scanv[j], 0); } while (val == 0);
        p += val - 1;
    }
    #pragma unroll
    for (int d = 16; d; d >>= 1) p += __shfl_down_sync(0xffffffffu, p, d);
    if ((tid & 31) == 0) red[tid >> 5] = p;
    __syncthreads();
    if (tid == 0) {
        int t = 0;
        #pragma unroll
        for (int w = 0; w < 8; w++) t += red[w];
        s_prefix = t;
    }
    __syncthreads();

    int excl = incl - vp + s_prefix;
    if (i < NN) {
        g_offs[i] = excl;
        g_cursor[i] = excl;
        g_dinv[i] = rsqrtf((float)v + 1.0f);
        float2 padrec = make_float2(__int_as_float(i * FD), 0.f);
        for (int j = v; j < vp; j++) g_edge[excl + j] = padrec;
        if (i == NN - 1) g_offs[NN] = excl + vp;
    }
}

// ---------------- CSR scatter: store (src*FD, weight) --------------------------
__global__ void k_scatter(const int* __restrict__ src,
                          const int* __restrict__ dst, int ne) {
    int i = blockIdx.x * blockDim.x + threadIdx.x;
    if (i < ne) {
        int d = dst[i];
        int sN = src[i];
        float w = g_dinv[d] * g_dinv[sN];
        int pos = atomicAdd(&g_cursor[d], 1);
        __stcs(&g_edge[pos], make_float2(__int_as_float(sN * FD), w));
    }
}

// ---- aggregation: 4 warps/node (feature-split x edge-split), block = 2 nodes ---
template <bool POST>
__device__ __forceinline__ void agg_body(const __half* __restrict__ hh,
                                         const float* __restrict__ bias,
                                         __half* __restrict__ outh,
                                         float* __restrict__ outf) {
    __shared__ float2 part[2][2][32];     // [nodeInBlk][fhalf][lane]
    int tid  = threadIdx.x;
    int w    = tid >> 5;                  // 0..7
    int lane = tid & 31;
    int nib  = w >> 2;                    // node within block
    int fh   = w & 1;                     // feature half
    int eh   = (w >> 1) & 1;              // edge half
    int node = blockIdx.x * 2 + nib;      // NN even -> always valid
    int coff = fh * 64 + lane * 2;
    int s = g_offs[node], e = g_offs[node + 1];    // multiple of 8
    int B  = (e - s) >> 3;
    int b0 = (B + 1) >> 1;
    int js = eh ? s + (b0 << 3) : s;
    int je = eh ? e : s + (b0 << 3);

    const __half* hb = hh + coff;
    float2 acc0 = make_float2(0.f, 0.f);
    float2 acc1 = make_float2(0.f, 0.f);

    for (int j = js; j < je; j += 8) {
        float2 ed[8];
        #pragma unroll
        for (int u = 0; u < 8; u++) ed[u] = __ldcs(&g_edge[j + u]);
        uint32_t q[8];
        #pragma unroll
        for (int u = 0; u < 8; u++)
            q[u] = *(const uint32_t*)(hb + __float_as_int(ed[u].x));
        #pragma unroll
        for (int u = 0; u < 8; u += 2) {
            float2 a = __half22float2(*(const __half2*)&q[u]);
            float2 b = __half22float2(*(const __half2*)&q[u + 1]);
            acc0.x = fmaf(ed[u].y, a.x, acc0.x);
            acc0.y = fmaf(ed[u].y, a.y, acc0.y);
            acc1.x = fmaf(ed[u + 1].y, b.x, acc1.x);
            acc1.y = fmaf(ed[u + 1].y, b.y, acc1.y);
        }
    }
    float2 r = make_float2(acc0.x + acc1.x, acc0.y + acc1.y);

    if (eh == 1) part[nib][fh][lane] = r;
    __syncthreads();
    if (eh == 0) {
        float2 p = part[nib][fh][lane];
        r.x += p.x; r.y += p.y;
        // self loop
        float di = g_dinv[node];
        float wd = di * di;
        float2 v = __half22float2(*(const __half2*)(hb + node * FD));
        r.x = fmaf(wd, v.x, r.x);
        r.y = fmaf(wd, v.y, r.y);
        if (POST) {
            float2 bv = *(const float2*)(bias + coff);
            r.x = fmaxf(r.x + bv.x, 0.f);
            r.y = fmaxf(r.y + bv.y, 0.f);
            __stcs((float2*)(outf + (size_t)node * FD + coff), r);
        } else {
            *(__half2*)(outh + (size_t)node * FD + coff) = __float22half2_rn(r);
        }
    }
}

__global__ void k_agg_pre(const __half* __restrict__ hh, __half* __restrict__ outh) {
    agg_body<false>(hh, nullptr, outh, nullptr);
}

__global__ void k_agg_post(const __half* __restrict__ hh, const float* __restrict__ bias,
                           float* __restrict__ outf) {
    agg_body<true>(hh, bias, nullptr, outf);
}

// ---------------- fp16 tensor-core GEMM: C[n,128] = A[n,128] @ W[128,128] ------
#define WT_STRIDE 136                       // halfs; Wt[n][k]
#define AS_STRIDE_H 56                      // halfs; 112B rows
#define A_CHUNK_HALFS (128 * AS_STRIDE_H)   // 7168
#define GEMM_SMEM ((128 * WT_STRIDE + 2 * A_CHUNK_HALFS) * 2)   // 63,488 B

__global__ __launch_bounds__(256, 2) void k_gemm_f16(const __half* __restrict__ A,
                                                     const float* __restrict__ W,
                                                     const float* __restrict__ bias,
                                                     __half* __restrict__ Ch, int nrows) {
    extern __shared__ __half smh[];
    __half* Wt = smh;                         // [128 n][136 k]
    __half* As = smh + 128 * WT_STRIDE;       // [2][128][56]

    int tid = threadIdx.x;
    int row0 = blockIdx.x * 128;
    uint32_t as_base = (uint32_t)__cvta_generic_to_shared(As);

    for (int i = tid; i < 128 * 32; i += 256) {
        int r = i >> 5, c = (i & 31) * 4;
        float4 v = ((const float4*)(W + (size_t)r * FD))[i & 31];
        Wt[(c + 0) * WT_STRIDE + r] = __float2half(v.x);
        Wt[(c + 1) * WT_STRIDE + r] = __float2half(v.y);
        Wt[(c + 2) * WT_STRIDE + r] = __float2half(v.z);
        Wt[(c + 3) * WT_STRIDE + r] = __float2half(v.w);
    }

    auto load_chunk = [&](int c, int buf) {
        #pragma unroll
        for (int i = 0; i < 2; i++) {
            int idx = tid + i * 256;
            int r = idx >> 2;
            int q = idx & 3;
            const __half* g = A + (size_t)(row0 + r) * FD + c * 32 + q * 8;
            uint32_t s = as_base + (uint32_t)(buf * A_CHUNK_HALFS + r * AS_STRIDE_H + q * 8) * 2;
            cp_async16(s, g, (row0 + r < nrows) ? 16 : 0);
        }
    };

    int lane = tid & 31;
    int wid  = tid >> 5;
    int wr = wid & 3;
    int wc = wid >> 2;
    int qrow = lane >> 2;
    int qcol = lane & 3;

    float acc[2][8][4];
    #pragma unroll
    for (int s = 0; s < 2; s++)
        #pragma unroll
        for (int t = 0; t < 8; t++)
            #pragma unroll
            for (int q = 0; q < 4; q++) acc[s][t][q] = 0.f;

    load_chunk(0, 0);
    asm volatile("cp.async.commit_group;" ::: "memory");

    #pragma unroll
    for (int c = 0; c < 4; c++) {
        int buf = c & 1;
        if (c < 3) {
            load_chunk(c + 1, buf ^ 1);
            asm volatile("cp.async.commit_group;" ::: "memory");
            asm volatile("cp.async.wait_group 1;" ::: "memory");
        } else {
            asm volatile("cp.async.wait_group 0;" ::: "memory");
        }
        __syncthreads();

        const __half* Ab = As + buf * A_CHUNK_HALFS;
        #pragma unroll
        for (int ks = 0; ks < 2; ks++) {
            int k0 = ks * 16;
            int K0 = c * 32 + k0;
            uint32_t a[2][4];
            #pragma unroll
            for (int s = 0; s < 2; s++) {
                int rb = 32 * wr + 16 * s + qrow;
                a[s][0] = *(const uint32_t*)&Ab[(rb)     * AS_STRIDE_H + k0 + 2 * qcol];
                a[s][1] = *(const uint32_t*)&Ab[(rb + 8) * AS_STRIDE_H + k0 + 2 * qcol];
                a[s][2] = *(const uint32_t*)&Ab[(rb)     * AS_STRIDE_H + k0 + 2 * qcol + 8];
                a[s][3] = *(const uint32_t*)&Ab[(rb + 8) * AS_STRIDE_H + k0 + 2 * qcol + 8];
            }
            #pragma unroll
            for (int t = 0; t < 8; t++) {
                int n = 64 * wc + 8 * t + qrow;
                uint32_t b0 = *(const uint32_t*)&Wt[n * WT_STRIDE + K0 + 2 * qcol];
                uint32_t b1 = *(const uint32_t*)&Wt[n * WT_STRIDE + K0 + 2 * qcol + 8];
                mma_f16(acc[0][t], a[0], b0, b1);
                mma_f16(acc[1][t], a[1], b0, b1);
            }
        }
        __syncthreads();
    }

    bool has_bias = (bias != nullptr);
    #pragma unroll
    for (int s = 0; s < 2; s++) {
        int rbase = row0 + 32 * wr + 16 * s + qrow;
        #pragma unroll
        for (int t = 0; t < 8; t++) {
            int col = 64 * wc + 8 * t + 2 * qcol;
            float2 lo = make_float2(acc[s][t][0], acc[s][t][1]);
            float2 hi = make_float2(acc[s][t][2], acc[s][t][3]);
            if (has_bias) {
                float b0 = bias[col], b1 = bias[col + 1];
                lo.x = fmaxf(lo.x + b0, 0.f); lo.y = fmaxf(lo.y + b1, 0.f);
                hi.x = fmaxf(hi.x + b0, 0.f); hi.y = fmaxf(hi.y + b1, 0.f);
            }
            if (rbase < nrows)
                *(__half2*)(Ch + (size_t)rbase * FD + col) = __float22half2_rn(lo);
            if (rbase + 8 < nrows)
                *(__half2*)(Ch + (size_t)(rbase + 8) * FD + col) = __float22half2_rn(hi);
        }
    }
}

// ---------------- per-graph mean pool: 1024 thr/graph, 8 row-stripes ------------
__global__ void k_pool(const float* __restrict__ h, const int* __restrict__ bat) {
    int g = blockIdx.x;
    __shared__ int se[2];
    __shared__ float part[7][FD];
    if (threadIdx.x < 2) {
        int target = g + threadIdx.x;
        int lo = 0, hi = NN;
        while (lo < hi) { int m = (lo + hi) >> 1; if (bat[m] < target) lo = m + 1; else hi = m; }
        se[threadIdx.x] = lo;
    }
    __syncthreads();
    int s = se[0], e = se[1];
    int c = threadIdx.x & 127;
    int r0 = threadIdx.x >> 7;
    float acc = 0.f;
    for (int i = s + r0; i < e; i += 8)
        acc += h[(size_t)i * FD + c];
    if (r0 > 0) part[r0 - 1][c] = acc;
    __syncthreads();
    if (r0 == 0) {
        #pragma unroll
        for (int u = 0; u < 7; u++) acc += part[u][c];
        float cnt = (float)((e - s) > 1 ? (e - s) : 1);
        g_pooled[g * FD + c] = acc / cnt;
    }
}

// ---------------- final FC -------------------------------------------------------
__global__ void k_fc(const float* __restrict__ fcW, const float* __restrict__ fcb,
                     float* __restrict__ out) {
    int g = blockIdx.x;
    int c = threadIdx.x;
    float acc = fcb[c];
    #pragma unroll 4
    for (int k = 0; k < FD; k++)
        acc = fmaf(g_pooled[g * FD + k], fcW[k * NC + c], acc);
    out[g * NC + c] = acc;
}

// ---------------- cleanup: restore zero g_deg for next replay -------------------
__global__ void k_cleanup() {
    int i = blockIdx.x * blockDim.x + threadIdx.x;
    if (i < NN) g_deg[i] = 0;
}

// ---------------- launch ----------------------------------------------------------
extern "C" void kernel_launch(void* const* d_in, const int* in_sizes, int n_in,
                              void* d_out, int out_size) {
    const float* x    = (const float*)d_in[0];
    const int*   ei   = (const int*)d_in[1];
    const int*   bat  = (const int*)d_in[2];
    const float* W1   = (const float*)d_in[3];
    const float* b1   = (const float*)d_in[4];
    const float* W2   = (const float*)d_in[5];
    const float* b2   = (const float*)d_in[6];
    const float* fcW  = (const float*)d_in[7];
    const float* fcb  = (const float*)d_in[8];
    float* out = (float*)d_out;

    int ne = in_sizes[1] / 2;
    const int* src = ei;
    const int* dst = ei + ne;

    float *bufB;
    __half *xh, *aggh, *h1h;
    cudaGetSymbolAddress((void**)&bufB, g_bufB);
    cudaGetSymbolAddress((void**)&xh, g_xh);
    cudaGetSymbolAddress((void**)&aggh, g_aggh);
    cudaGetSymbolAddress((void**)&h1h, g_h1h);

    cudaFuncSetAttribute(k_gemm_f16, cudaFuncAttributeMaxDynamicSharedMemorySize, GEMM_SMEM);

    int tb = 256;
    int gbN   = (NN + tb - 1) / tb;
    int gbE   = (ne + tb - 1) / tb;
    int gbAgg = NN / 2;                       // 2 nodes per block, 4 warps/node
    int gbGemm = (NN + 127) / 128;

    k_deg_x2h<<<gbE, tb>>>(dst, ne, x);                               // 0
    k_scan<<<NBLK, tb>>>();                                           // 1 (+pad fill)
    k_scatter<<<gbE, tb>>>(src, dst, ne);                             // 2
    k_agg_pre<<<gbAgg, tb>>>(xh, aggh);                               // 3 <- profiled
    k_gemm_f16<<<gbGemm, tb, GEMM_SMEM>>>(aggh, W1, b1, h1h, NN);     // 4 (bias+relu)
    k_gemm_f16<<<gbGemm, tb, GEMM_SMEM>>>(h1h, W2, nullptr, aggh, NN);// 5 (plain)
    k_agg_post<<<gbAgg, tb>>>(aggh, b2, bufB);                        // 6 (bias+relu)
    k_pool<<<NG, 1024>>>(bufB, bat);                                  // 7
    k_fc<<<NG, NC>>>(fcW, fcb, out);                                  // 8
    k_cleanup<<<gbN, tb>>>();                                         // 9
}

// round 16
// speedup vs baseline: 1.2394x; 1.2394x over previous
#include <cuda_runtime.h>
#include <cuda_fp16.h>
#include <cstdint>

#define NN 100000
#define NE 1600000
#define FD 128
#define NG 64
#define NC 32

#define NBLK ((NN + 255) / 256)        // 391 scan blocks
#define NEPAD (NE + 8 * NN)            // padded edge capacity

// ---------------- scratch (static device globals; allocation-free) ----------
// g_deg zero at start (static init); k_scan re-zeros it after reading each
// launch (replay-safe: next reader is next replay's k_deg_x2h). g_scanv
// re-zeroed by k_deg_x2h before every k_scan (same-stream ordering).
__device__ int    g_deg[NN];
__device__ int    g_offs[NN + 1];
__device__ int    g_cursor[NN];
__device__ float2 g_edge[NEPAD];       // (.x = bitcast(src*FD), .y = weight)
__device__ float  g_dinv[NN];
__device__ int    g_scanv[NBLK];
__device__ __half g_xh[(size_t)NN * FD];      // fp16 X
__device__ __half g_aggh[(size_t)NN * FD];    // agg1 out / gemm2 out (reused)
__device__ __half g_h1h[(size_t)NN * FD];     // gemm1 out (relu'd h1)
__device__ float  g_bufB[(size_t)NN * FD];    // agg2 out fp32
__device__ float  g_pooled[NG * FD];

// ---------------- helpers -----------------------------------------------------
__device__ __forceinline__ void mma_f16(float* d, const uint32_t* a, uint32_t b0, uint32_t b1) {
    asm volatile("mma.sync.aligned.m16n8k16.row.col.f32.f16.f16.f32 "
                 "{%0,%1,%2,%3}, {%4,%5,%6,%7}, {%8,%9}, {%0,%1,%2,%3};"
                 : "+f"(d[0]), "+f"(d[1]), "+f"(d[2]), "+f"(d[3])
                 : "r"(a[0]), "r"(a[1]), "r"(a[2]), "r"(a[3]), "r"(b0), "r"(b1));
}

__device__ __forceinline__ void cp_async16(uint32_t saddr, const void* gptr, int src_bytes) {
    asm volatile("cp.async.ca.shared.global [%0], [%1], 16, %2;"
                 :: "r"(saddr), "l"(gptr), "r"(src_bytes));
}

// ---------------- deg histogram + x->fp16 + scan-flag reset --------------------
__global__ void k_deg_x2h(const int* __restrict__ dst, int ne,
                          const float* __restrict__ x) {
    int gid = blockIdx.x * blockDim.x + threadIdx.x;
    int stride = gridDim.x * blockDim.x;
    if (gid < ne) atomicAdd(&g_deg[dst[gid]], 1);
    if (gid < NBLK) g_scanv[gid] = 0;
    for (int i = gid; i < NN * FD / 2; i += stride) {
        float2 v = ((const float2*)x)[i];
        ((__half2*)g_xh)[i] = __float22half2_rn(v);
    }
}

// ------ single-kernel scan over PADDED degrees + pad fill + deg cleanup --------
__global__ void k_scan() {
    __shared__ int warp_sums[8];
    __shared__ int red[8];
    __shared__ int s_prefix;
    int tid = threadIdx.x, bid = blockIdx.x;
    int i = bid * 256 + tid;
    int v  = (i < NN) ? g_deg[i] : 0;
    int vp = (v + 7) & ~7;                 // padded degree

    int x = vp;
    #pragma unroll
    for (int d = 1; d < 32; d <<= 1) {
        int y = __shfl_up_sync(0xffffffffu, x, d);
        if ((tid & 31) >= d) x += y;
    }
    if ((tid & 31) == 31) warp_sums[tid >> 5] = x;
    __syncthreads();
    if (tid < 8) {
        int y = warp_sums[tid];
        #pragma unroll
        for (int d = 1; d < 8; d <<= 1) {
            int z = __shfl_up_sync(0xffu, y, d);
            if (tid >= d) y += z;
        }
        warp_sums[tid] = y;
    }
    __syncthreads();
    int incl = x + ((tid >= 32) ? warp_sums[(tid >> 5) - 1] : 0);

    if (tid == 255) atomicExch(&g_scanv[bid], incl + 1);   // publish (+1 sentinel)

    int p = 0;
    for (int j = tid; j < bid; j += 256) {
        int val;
        do { val = atomicAdd(&g_scanv[j], 0); } while (val == 0);
        p += val - 1;
    }
    #pragma unroll
    for (int d = 16; d; d >>= 1) p += __shfl_down_sync(0xffffffffu, p, d);
    if ((tid & 31) == 0) red[tid >> 5] = p;
    __syncthreads();
    if (tid == 0) {
        int t = 0;
        #pragma unroll
        for (int w = 0; w < 8; w++) t += red[w];
        s_prefix = t;
    }
    __syncthreads();

    int excl = incl - vp + s_prefix;
    if (i < NN) {
        g_offs[i] = excl;
        g_cursor[i] = excl;
        g_dinv[i] = rsqrtf((float)v + 1.0f);
        g_deg[i] = 0;                       // fused cleanup for next replay
        float2 padrec = make_float2(__int_as_float(i * FD), 0.f);
        for (int j = v; j < vp; j++) g_edge[excl + j] = padrec;
        if (i == NN - 1) g_offs[NN] = excl + vp;
    }
}

// ---------------- CSR scatter: store (src*FD, weight) --------------------------
__global__ void k_scatter(const int* __restrict__ src,
                          const int* __restrict__ dst, int ne) {
    int i = blockIdx.x * blockDim.x + threadIdx.x;
    if (i < ne) {
        int d = dst[i];
        int sN = src[i];
        float w = g_dinv[d] * g_dinv[sN];
        int pos = atomicAdd(&g_cursor[d], 1);
        __stcs(&g_edge[pos], make_float2(__int_as_float(sN * FD), w));
    }
}

// ------ aggregation: 1 warp/node, 8B gathers (full row), padded, no clamps -----
template <bool POST>
__device__ __forceinline__ void agg_body(const __half* __restrict__ hh,
                                         const float* __restrict__ bias,
                                         __half* __restrict__ outh,
                                         float* __restrict__ outf) {
    int node = (blockIdx.x * blockDim.x + threadIdx.x) >> 5;
    if (node >= NN) return;
    int lane = threadIdx.x & 31;
    int coff = lane * 4;                       // 4 fp16 cols per lane
    int s = g_offs[node], e = g_offs[node + 1];   // multiple of 8

    const __half* hb = hh + coff;
    float2 acc0a = make_float2(0.f, 0.f), acc0b = make_float2(0.f, 0.f);
    float2 acc1a = make_float2(0.f, 0.f), acc1b = make_float2(0.f, 0.f);

    for (int j = s; j < e; j += 8) {
        float2 ed[8];
        #pragma unroll
        for (int u = 0; u < 8; u++) ed[u] = __ldcs(&g_edge[j + u]);
        uint2 q[8];
        #pragma unroll
        for (int u = 0; u < 8; u++)
            q[u] = *(const uint2*)(hb + __float_as_int(ed[u].x));
        #pragma unroll
        for (int u = 0; u < 8; u += 2) {
            float2 a01 = __half22float2(*(const __half2*)&q[u].x);
            float2 a23 = __half22float2(*(const __half2*)&q[u].y);
            float2 b01 = __half22float2(*(const __half2*)&q[u + 1].x);
            float2 b23 = __half22float2(*(const __half2*)&q[u + 1].y);
            acc0a.x = fmaf(ed[u].y, a01.x, acc0a.x);
            acc0a.y = fmaf(ed[u].y, a01.y, acc0a.y);
            acc0b.x = fmaf(ed[u].y, a23.x, acc0b.x);
            acc0b.y = fmaf(ed[u].y, a23.y, acc0b.y);
            acc1a.x = fmaf(ed[u + 1].y, b01.x, acc1a.x);
            acc1a.y = fmaf(ed[u + 1].y, b01.y, acc1a.y);
            acc1b.x = fmaf(ed[u + 1].y, b23.x, acc1b.x);
            acc1b.y = fmaf(ed[u + 1].y, b23.y, acc1b.y);
        }
    }
    {   // self loop
        float di = g_dinv[node];
        float w = di * di;
        uint2 qv = *(const uint2*)(hb + node * FD);
        float2 v01 = __half22float2(*(const __half2*)&qv.x);
        float2 v23 = __half22float2(*(const __half2*)&qv.y);
        acc0a.x = fmaf(w, v01.x, acc0a.x);
        acc0a.y = fmaf(w, v01.y, acc0a.y);
        acc0b.x = fmaf(w, v23.x, acc0b.x);
        acc0b.y = fmaf(w, v23.y, acc0b.y);
    }
    float4 r;
    r.x = acc0a.x + acc1a.x;
    r.y = acc0a.y + acc1a.y;
    r.z = acc0b.x + acc1b.x;
    r.w = acc0b.y + acc1b.y;
    if (POST) {
        float4 bv = *(const float4*)(bias + coff);
        r.x = fmaxf(r.x + bv.x, 0.f);
        r.y = fmaxf(r.y + bv.y, 0.f);
        r.z = fmaxf(r.z + bv.z, 0.f);
        r.w = fmaxf(r.w + bv.w, 0.f);
        __stcs((float4*)(outf + (size_t)node * FD + coff), r);
    } else {
        __half2 h01 = __float22half2_rn(make_float2(r.x, r.y));
        __half2 h23 = __float22half2_rn(make_float2(r.z, r.w));
        uint2 pk;
        pk.x = *(const uint32_t*)&h01;
        pk.y = *(const uint32_t*)&h23;
        *(uint2*)(outh + (size_t)node * FD + coff) = pk;
    }
}

__global__ void k_agg_pre(const __half* __restrict__ hh, __half* __restrict__ outh) {
    agg_body<false>(hh, nullptr, outh, nullptr);
}

__global__ void k_agg_post(const __half* __restrict__ hh, const float* __restrict__ bias,
                           float* __restrict__ outf) {
    agg_body<true>(hh, bias, nullptr, outf);
}

// ---------------- fp16 tensor-core GEMM: C[n,128] = A[n,128] @ W[128,128] ------
#define WT_STRIDE 136                       // halfs; Wt[n][k]
#define AS_STRIDE_H 56                      // halfs; 112B rows
#define A_CHUNK_HALFS (128 * AS_STRIDE_H)   // 7168
#define GEMM_SMEM ((128 * WT_STRIDE + 2 * A_CHUNK_HALFS) * 2)   // 63,488 B

__global__ __launch_bounds__(256, 2) void k_gemm_f16(const __half* __restrict__ A,
                                                     const float* __restrict__ W,
                                                     const float* __restrict__ bias,
                                                     __half* __restrict__ Ch, int nrows) {
    extern __shared__ __half smh[];
    __half* Wt = smh;                         // [128 n][136 k]
    __half* As = smh + 128 * WT_STRIDE;       // [2][128][56]

    int tid = threadIdx.x;
    int row0 = blockIdx.x * 128;
    uint32_t as_base = (uint32_t)__cvta_generic_to_shared(As);

    for (int i = tid; i < 128 * 32; i += 256) {
        int r = i >> 5, c = (i & 31) * 4;
        float4 v = ((const float4*)(W + (size_t)r * FD))[i & 31];
        Wt[(c + 0) * WT_STRIDE + r] = __float2half(v.x);
        Wt[(c + 1) * WT_STRIDE + r] = __float2half(v.y);
        Wt[(c + 2) * WT_STRIDE + r] = __float2half(v.z);
        Wt[(c + 3) * WT_STRIDE + r] = __float2half(v.w);
    }

    auto load_chunk = [&](int c, int buf) {
        #pragma unroll
        for (int i = 0; i < 2; i++) {
            int idx = tid + i * 256;
            int r = idx >> 2;
            int q = idx & 3;
            const __half* g = A + (size_t)(row0 + r) * FD + c * 32 + q * 8;
            uint32_t s = as_base + (uint32_t)(buf * A_CHUNK_HALFS + r * AS_STRIDE_H + q * 8) * 2;
            cp_async16(s, g, (row0 + r < nrows) ? 16 : 0);
        }
    };

    int lane = tid & 31;
    int wid  = tid >> 5;
    int wr = wid & 3;
    int wc = wid >> 2;
    int qrow = lane >> 2;
    int qcol = lane & 3;

    float acc[2][8][4];
    #pragma unroll
    for (int s = 0; s < 2; s++)
        #pragma unroll
        for (int t = 0; t < 8; t++)
            #pragma unroll
            for (int q = 0; q < 4; q++) acc[s][t][q] = 0.f;

    load_chunk(0, 0);
    asm volatile("cp.async.commit_group;" ::: "memory");

    #pragma unroll
    for (int c = 0; c < 4; c++) {
        int buf = c & 1;
        if (c < 3) {
            load_chunk(c + 1, buf ^ 1);
            asm volatile("cp.async.commit_group;" ::: "memory");
            asm volatile("cp.async.wait_group 1;" ::: "memory");
        } else {
            asm volatile("cp.async.wait_group 0;" ::: "memory");
        }
        __syncthreads();

        const __half* Ab = As + buf * A_CHUNK_HALFS;
        #pragma unroll
        for (int ks = 0; ks < 2; ks++) {
            int k0 = ks * 16;
            int K0 = c * 32 + k0;
            uint32_t a[2][4];
            #pragma unroll
            for (int s = 0; s < 2; s++) {
                int rb = 32 * wr + 16 * s + qrow;
                a[s][0] = *(const uint32_t*)&Ab[(rb)     * AS_STRIDE_H + k0 + 2 * qcol];
                a[s][1] = *(const uint32_t*)&Ab[(rb + 8) * AS_STRIDE_H + k0 + 2 * qcol];
                a[s][2] = *(const uint32_t*)&Ab[(rb)     * AS_STRIDE_H + k0 + 2 * qcol + 8];
                a[s][3] = *(const uint32_t*)&Ab[(rb + 8) * AS_STRIDE_H + k0 + 2 * qcol + 8];
            }
            #pragma unroll
            for (int t = 0; t < 8; t++) {
                int n = 64 * wc + 8 * t + qrow;
                uint32_t b0 = *(const uint32_t*)&Wt[n * WT_STRIDE + K0 + 2 * qcol];
                uint32_t b1 = *(const uint32_t*)&Wt[n * WT_STRIDE + K0 + 2 * qcol + 8];
                mma_f16(acc[0][t], a[0], b0, b1);
                mma_f16(acc[1][t], a[1], b0, b1);
            }
        }
        __syncthreads();
    }

    bool has_bias = (bias != nullptr);
    #pragma unroll
    for (int s = 0; s < 2; s++) {
        int rbase = row0 + 32 * wr + 16 * s + qrow;
        #pragma unroll
        for (int t = 0; t < 8; t++) {
            int col = 64 * wc + 8 * t + 2 * qcol;
            float2 lo = make_float2(acc[s][t][0], acc[s][t][1]);
            float2 hi = make_float2(acc[s][t][2], acc[s][t][3]);
            if (has_bias) {
                float b0 = bias[col], b1 = bias[col + 1];
                lo.x = fmaxf(lo.x + b0, 0.f); lo.y = fmaxf(lo.y + b1, 0.f);
                hi.x = fmaxf(hi.x + b0, 0.f); hi.y = fmaxf(hi.y + b1, 0.f);
            }
            if (rbase < nrows)
                *(__half2*)(Ch + (size_t)rbase * FD + col) = __float22half2_rn(lo);
            if (rbase + 8 < nrows)
                *(__half2*)(Ch + (size_t)(rbase + 8) * FD + col) = __float22half2_rn(hi);
        }
    }
}

// ---------------- per-graph mean pool: 1024 thr/graph, 8 row-stripes ------------
__global__ void k_pool(const float* __restrict__ h, const int* __restrict__ bat) {
    int g = blockIdx.x;
    __shared__ int se[2];
    __shared__ float part[7][FD];
    if (threadIdx.x < 2) {
        int target = g + threadIdx.x;
        int lo = 0, hi = NN;
        while (lo < hi) { int m = (lo + hi) >> 1; if (bat[m] < target) lo = m + 1; else hi = m; }
        se[threadIdx.x] = lo;
    }
    __syncthreads();
    int s = se[0], e = se[1];
    int c = threadIdx.x & 127;
    int r0 = threadIdx.x >> 7;
    float acc = 0.f;
    for (int i = s + r0; i < e; i += 8)
        acc += h[(size_t)i * FD + c];
    if (r0 > 0) part[r0 - 1][c] = acc;
    __syncthreads();
    if (r0 == 0) {
        #pragma unroll
        for (int u = 0; u < 7; u++) acc += part[u][c];
        float cnt = (float)((e - s) > 1 ? (e - s) : 1);
        g_pooled[g * FD + c] = acc / cnt;
    }
}

// ---------------- final FC -------------------------------------------------------
__global__ void k_fc(const float* __restrict__ fcW, const float* __restrict__ fcb,
                     float* __restrict__ out) {
    int g = blockIdx.x;
    int c = threadIdx.x;
    float acc = fcb[c];
    #pragma unroll 4
    for (int k = 0; k < FD; k++)
        acc = fmaf(g_pooled[g * FD + k], fcW[k * NC + c], acc);
    out[g * NC + c] = acc;
}

// ---------------- launch ----------------------------------------------------------
extern "C" void kernel_launch(void* const* d_in, const int* in_sizes, int n_in,
                              void* d_out, int out_size) {
    const float* x    = (const float*)d_in[0];
    const int*   ei   = (const int*)d_in[1];
    const int*   bat  = (const int*)d_in[2];
    const float* W1   = (const float*)d_in[3];
    const float* b1   = (const float*)d_in[4];
    const float* W2   = (const float*)d_in[5];
    const float* b2   = (const float*)d_in[6];
    const float* fcW  = (const float*)d_in[7];
    const float* fcb  = (const float*)d_in[8];
    float* out = (float*)d_out;

    int ne = in_sizes[1] / 2;
    const int* src = ei;
    const int* dst = ei + ne;

    float *bufB;
    __half *xh, *aggh, *h1h;
    cudaGetSymbolAddress((void**)&bufB, g_bufB);
    cudaGetSymbolAddress((void**)&xh, g_xh);
    cudaGetSymbolAddress((void**)&aggh, g_aggh);
    cudaGetSymbolAddress((void**)&h1h, g_h1h);

    cudaFuncSetAttribute(k_gemm_f16, cudaFuncAttributeMaxDynamicSharedMemorySize, GEMM_SMEM);

    int tb = 256;
    int gbE   = (ne + tb - 1) / tb;
    int gbAgg = (NN * 32 + tb - 1) / tb;      // 1 warp per node
    int gbGemm = (NN + 127) / 128;

    k_deg_x2h<<<gbE, tb>>>(dst, ne, x);                               // 0
    k_scan<<<NBLK, tb>>>();                                           // 1 (+pad, +cleanup)
    k_scatter<<<gbE, tb>>>(src, dst, ne);                             // 2
    k_agg_pre<<<gbAgg, tb>>>(xh, aggh);                               // 3 <- profiled
    k_gemm_f16<<<gbGemm, tb, GEMM_SMEM>>>(aggh, W1, b1, h1h, NN);     // 4 (bias+relu)
    k_gemm_f16<<<gbGemm, tb, GEMM_SMEM>>>(h1h, W2, nullptr, aggh, NN);// 5 (plain)
    k_agg_post<<<gbAgg, tb>>>(aggh, b2, bufB);                        // 6 (bias+relu)
    k_pool<<<NG, 1024>>>(bufB, bat);                                  // 7
    k_fc<<<NG, NC>>>(fcW, fcb, out);                                  // 8
}

// round 17
// speedup vs baseline: 1.2585x; 1.0155x over previous
#include <cuda_runtime.h>
#include <cuda_fp16.h>
#include <cstdint>

#define NN 100000
#define NE 1600000
#define FD 128
#define NG 64
#define NC 32

#define NBLK ((NN + 255) / 256)        // 391 scan blocks
#define NEPAD (NE + 8 * NN)            // padded edge capacity

// ---------------- scratch (static device globals; allocation-free) ----------
// g_deg zero at start (static init); k_scan re-zeros it after reading each
// launch (replay-safe: next reader is next replay's k_deg_x2h). g_scanv
// re-zeroed by k_deg_x2h before every k_scan (same-stream ordering).
__device__ int    g_deg[NN];
__device__ int    g_offs[NN + 1];
__device__ int    g_cursor[NN];
__device__ float2 g_edge[NEPAD];       // (.x = bitcast(src*FD), .y = bitcast half2(w,w))
__device__ float  g_dinv[NN];
__device__ int    g_scanv[NBLK];
__device__ __half g_xh[(size_t)NN * FD];      // fp16 X
__device__ __half g_aggh[(size_t)NN * FD];    // agg1 out / gemm2 out (reused)
__device__ __half g_h1h[(size_t)NN * FD];     // gemm1 out (relu'd h1)
__device__ float  g_bufB[(size_t)NN * FD];    // agg2 out fp32
__device__ float  g_pooled[NG * FD];

// ---------------- helpers -----------------------------------------------------
__device__ __forceinline__ void mma_f16(float* d, const uint32_t* a, uint32_t b0, uint32_t b1) {
    asm volatile("mma.sync.aligned.m16n8k16.row.col.f32.f16.f16.f32 "
                 "{%0,%1,%2,%3}, {%4,%5,%6,%7}, {%8,%9}, {%0,%1,%2,%3};"
                 : "+f"(d[0]), "+f"(d[1]), "+f"(d[2]), "+f"(d[3])
                 : "r"(a[0]), "r"(a[1]), "r"(a[2]), "r"(a[3]), "r"(b0), "r"(b1));
}

__device__ __forceinline__ void cp_async16(uint32_t saddr, const void* gptr, int src_bytes) {
    asm volatile("cp.async.ca.shared.global [%0], [%1], 16, %2;"
                 :: "r"(saddr), "l"(gptr), "r"(src_bytes));
}

// ---------------- deg histogram + x->fp16 + scan-flag reset --------------------
__global__ void k_deg_x2h(const int* __restrict__ dst, int ne,
                          const float* __restrict__ x) {
    int gid = blockIdx.x * blockDim.x + threadIdx.x;
    int stride = gridDim.x * blockDim.x;
    if (gid < ne) atomicAdd(&g_deg[dst[gid]], 1);
    if (gid < NBLK) g_scanv[gid] = 0;
    for (int i = gid; i < NN * FD / 2; i += stride) {
        float2 v = ((const float2*)x)[i];
        ((__half2*)g_xh)[i] = __float22half2_rn(v);
    }
}

// ------ single-kernel scan over PADDED degrees + pad fill + deg cleanup --------
__global__ void k_scan() {
    __shared__ int warp_sums[8];
    __shared__ int red[8];
    __shared__ int s_prefix;
    int tid = threadIdx.x, bid = blockIdx.x;
    int i = bid * 256 + tid;
    int v  = (i < NN) ? g_deg[i] : 0;
    int vp = (v + 7) & ~7;                 // padded degree

    int x = vp;
    #pragma unroll
    for (int d = 1; d < 32; d <<= 1) {
        int y = __shfl_up_sync(0xffffffffu, x, d);
        if ((tid & 31) >= d) x += y;
    }
    if ((tid & 31) == 31) warp_sums[tid >> 5] = x;
    __syncthreads();
    if (tid < 8) {
        int y = warp_sums[tid];
        #pragma unroll
        for (int d = 1; d < 8; d <<= 1) {
            int z = __shfl_up_sync(0xffu, y, d);
            if (tid >= d) y += z;
        }
        warp_sums[tid] = y;
    }
    __syncthreads();
    int incl = x + ((tid >= 32) ? warp_sums[(tid >> 5) - 1] : 0);

    if (tid == 255) atomicExch(&g_scanv[bid], incl + 1);   // publish (+1 sentinel)

    int p = 0;
    for (int j = tid; j < bid; j += 256) {
        int val;
        do { val = atomicAdd(&g_scanv[j], 0); } while (val == 0);
        p += val - 1;
    }
    #pragma unroll
    for (int d = 16; d; d >>= 1) p += __shfl_down_sync(0xffffffffu, p, d);
    if ((tid & 31) == 0) red[tid >> 5] = p;
    __syncthreads();
    if (tid == 0) {
        int t = 0;
        #pragma unroll
        for (int w = 0; w < 8; w++) t += red[w];
        s_prefix = t;
    }
    __syncthreads();

    int excl = incl - vp + s_prefix;
    if (i < NN) {
        g_offs[i] = excl;
        g_cursor[i] = excl;
        g_dinv[i] = rsqrtf((float)v + 1.0f);
        g_deg[i] = 0;                       // fused cleanup for next replay
        float2 padrec = make_float2(__int_as_float(i * FD), 0.f);  // half2(0,0)
        for (int j = v; j < vp; j++) g_edge[excl + j] = padrec;
        if (i == NN - 1) g_offs[NN] = excl + vp;
    }
}

// ---------------- CSR scatter: store (src*FD, half2(w,w)) ----------------------
__global__ void k_scatter(const int* __restrict__ src,
                          const int* __restrict__ dst, int ne) {
    int i = blockIdx.x * blockDim.x + threadIdx.x;
    if (i < ne) {
        int d = dst[i];
        int sN = src[i];
        float w = g_dinv[d] * g_dinv[sN];
        __half2 w2 = __float2half2_rn(w);
        int pos = atomicAdd(&g_cursor[d], 1);
        __stcs(&g_edge[pos], make_float2(__int_as_float(sN * FD),
                                         __uint_as_float(*(const uint32_t*)&w2)));
    }
}

// ------ aggregation: 1 warp/node, hfma2 intra-batch, fp32 across batches -------
template <bool POST>
__device__ __forceinline__ void agg_body(const __half* __restrict__ hh,
                                         const float* __restrict__ bias,
                                         __half* __restrict__ outh,
                                         float* __restrict__ outf) {
    int node = (blockIdx.x * blockDim.x + threadIdx.x) >> 5;
    if (node >= NN) return;
    int lane = threadIdx.x & 31;
    int coff = lane * 4;                       // 4 fp16 cols per lane
    int s = g_offs[node], e = g_offs[node + 1];   // multiple of 8 (64B aligned)

    const __half* hb = hh + coff;
    float4 acc = make_float4(0.f, 0.f, 0.f, 0.f);

    for (int j = s; j < e; j += 8) {
        float4 e4[4];                          // 2 edges per float4
        const float4* ep = (const float4*)(g_edge + j);
        #pragma unroll
        for (int u = 0; u < 4; u++) e4[u] = __ldcs(ep + u);
        uint2 q[8];
        q[0] = *(const uint2*)(hb + __float_as_int(e4[0].x));
        q[1] = *(const uint2*)(hb + __float_as_int(e4[0].z));
        q[2] = *(const uint2*)(hb + __float_as_int(e4[1].x));
        q[3] = *(const uint2*)(hb + __float_as_int(e4[1].z));
        q[4] = *(const uint2*)(hb + __float_as_int(e4[2].x));
        q[5] = *(const uint2*)(hb + __float_as_int(e4[2].z));
        q[6] = *(const uint2*)(hb + __float_as_int(e4[3].x));
        q[7] = *(const uint2*)(hb + __float_as_int(e4[3].z));

        uint32_t wb[8];
        wb[0] = __float_as_uint(e4[0].y); wb[1] = __float_as_uint(e4[0].w);
        wb[2] = __float_as_uint(e4[1].y); wb[3] = __float_as_uint(e4[1].w);
        wb[4] = __float_as_uint(e4[2].y); wb[5] = __float_as_uint(e4[2].w);
        wb[6] = __float_as_uint(e4[3].y); wb[7] = __float_as_uint(e4[3].w);

        __half2 h01 = __float2half2_rn(0.f);
        __half2 h23 = __float2half2_rn(0.f);
        #pragma unroll
        for (int u = 0; u < 8; u++) {
            __half2 w2 = *(const __half2*)&wb[u];
            h01 = __hfma2(w2, *(const __half2*)&q[u].x, h01);
            h23 = __hfma2(w2, *(const __half2*)&q[u].y, h23);
        }
        float2 f01 = __half22float2(h01);
        float2 f23 = __half22float2(h23);
        acc.x += f01.x; acc.y += f01.y;
        acc.z += f23.x; acc.w += f23.y;
    }
    {   // self loop in fp32 (exact weight)
        float di = g_dinv[node];
        float w = di * di;
        uint2 qv = *(const uint2*)(hb + node * FD);
        float2 v01 = __half22float2(*(const __half2*)&qv.x);
        float2 v23 = __half22float2(*(const __half2*)&qv.y);
        acc.x = fmaf(w, v01.x, acc.x);
        acc.y = fmaf(w, v01.y, acc.y);
        acc.z = fmaf(w, v23.x, acc.z);
        acc.w = fmaf(w, v23.y, acc.w);
    }
    if (POST) {
        float4 bv = *(const float4*)(bias + coff);
        acc.x = fmaxf(acc.x + bv.x, 0.f);
        acc.y = fmaxf(acc.y + bv.y, 0.f);
        acc.z = fmaxf(acc.z + bv.z, 0.f);
        acc.w = fmaxf(acc.w + bv.w, 0.f);
        __stcs((float4*)(outf + (size_t)node * FD + coff), acc);
    } else {
        __half2 o01 = __float22half2_rn(make_float2(acc.x, acc.y));
        __half2 o23 = __float22half2_rn(make_float2(acc.z, acc.w));
        uint2 pk;
        pk.x = *(const uint32_t*)&o01;
        pk.y = *(const uint32_t*)&o23;
        *(uint2*)(outh + (size_t)node * FD + coff) = pk;
    }
}

__global__ void k_agg_pre(const __half* __restrict__ hh, __half* __restrict__ outh) {
    agg_body<false>(hh, nullptr, outh, nullptr);
}

__global__ void k_agg_post(const __half* __restrict__ hh, const float* __restrict__ bias,
                           float* __restrict__ outf) {
    agg_body<true>(hh, bias, nullptr, outf);
}

// ---------------- fp16 tensor-core GEMM: C[n,128] = A[n,128] @ W[128,128] ------
#define WT_STRIDE 136                       // halfs; Wt[n][k]
#define AS_STRIDE_H 56                      // halfs; 112B rows
#define A_CHUNK_HALFS (128 * AS_STRIDE_H)   // 7168
#define GEMM_SMEM ((128 * WT_STRIDE + 2 * A_CHUNK_HALFS) * 2)   // 63,488 B

__global__ __launch_bounds__(256, 2) void k_gemm_f16(const __half* __restrict__ A,
                                                     const float* __restrict__ W,
                                                     const float* __restrict__ bias,
                                                     __half* __restrict__ Ch, int nrows) {
    extern __shared__ __half smh[];
    __half* Wt = smh;                         // [128 n][136 k]
    __half* As = smh + 128 * WT_STRIDE;       // [2][128][56]

    int tid = threadIdx.x;
    int row0 = blockIdx.x * 128;
    uint32_t as_base = (uint32_t)__cvta_generic_to_shared(As);

    for (int i = tid; i < 128 * 32; i += 256) {
        int r = i >> 5, c = (i & 31) * 4;
        float4 v = ((const float4*)(W + (size_t)r * FD))[i & 31];
        Wt[(c + 0) * WT_STRIDE + r] = __float2half(v.x);
        Wt[(c + 1) * WT_STRIDE + r] = __float2half(v.y);
        Wt[(c + 2) * WT_STRIDE + r] = __float2half(v.z);
        Wt[(c + 3) * WT_STRIDE + r] = __float2half(v.w);
    }

    auto load_chunk = [&](int c, int buf) {
        #pragma unroll
        for (int i = 0; i < 2; i++) {
            int idx = tid + i * 256;
            int r = idx >> 2;
            int q = idx & 3;
            const __half* g = A + (size_t)(row0 + r) * FD + c * 32 + q * 8;
            uint32_t s = as_base + (uint32_t)(buf * A_CHUNK_HALFS + r * AS_STRIDE_H + q * 8) * 2;
            cp_async16(s, g, (row0 + r < nrows) ? 16 : 0);
        }
    };

    int lane = tid & 31;
    int wid  = tid >> 5;
    int wr = wid & 3;
    int wc = wid >> 2;
    int qrow = lane >> 2;
    int qcol = lane & 3;

    float acc[2][8][4];
    #pragma unroll
    for (int s = 0; s < 2; s++)
        #pragma unroll
        for (int t = 0; t < 8; t++)
            #pragma unroll
            for (int q = 0; q < 4; q++) acc[s][t][q] = 0.f;

    load_chunk(0, 0);
    asm volatile("cp.async.commit_group;" ::: "memory");

    #pragma unroll
    for (int c = 0; c < 4; c++) {
        int buf = c & 1;
        if (c < 3) {
            load_chunk(c + 1, buf ^ 1);
            asm volatile("cp.async.commit_group;" ::: "memory");
            asm volatile("cp.async.wait_group 1;" ::: "memory");
        } else {
            asm volatile("cp.async.wait_group 0;" ::: "memory");
        }
        __syncthreads();

        const __half* Ab = As + buf * A_CHUNK_HALFS;
        #pragma unroll
        for (int ks = 0; ks < 2; ks++) {
            int k0 = ks * 16;
            int K0 = c * 32 + k0;
            uint32_t a[2][4];
            #pragma unroll
            for (int s = 0; s < 2; s++) {
                int rb = 32 * wr + 16 * s + qrow;
                a[s][0] = *(const uint32_t*)&Ab[(rb)     * AS_STRIDE_H + k0 + 2 * qcol];
                a[s][1] = *(const uint32_t*)&Ab[(rb + 8) * AS_STRIDE_H + k0 + 2 * qcol];
                a[s][2] = *(const uint32_t*)&Ab[(rb)     * AS_STRIDE_H + k0 + 2 * qcol + 8];
                a[s][3] = *(const uint32_t*)&Ab[(rb + 8) * AS_STRIDE_H + k0 + 2 * qcol + 8];
            }
            #pragma unroll
            for (int t = 0; t < 8; t++) {
                int n = 64 * wc + 8 * t + qrow;
                uint32_t b0 = *(const uint32_t*)&Wt[n * WT_STRIDE + K0 + 2 * qcol];
                uint32_t b1 = *(const uint32_t*)&Wt[n * WT_STRIDE + K0 + 2 * qcol + 8];
                mma_f16(acc[0][t], a[0], b0, b1);
                mma_f16(acc[1][t], a[1], b0, b1);
            }
        }
        __syncthreads();
    }

    bool has_bias = (bias != nullptr);
    #pragma unroll
    for (int s = 0; s < 2; s++) {
        int rbase = row0 + 32 * wr + 16 * s + qrow;
        #pragma unroll
        for (int t = 0; t < 8; t++) {
            int col = 64 * wc + 8 * t + 2 * qcol;
            float2 lo = make_float2(acc[s][t][0], acc[s][t][1]);
            float2 hi = make_float2(acc[s][t][2], acc[s][t][3]);
            if (has_bias) {
                float b0 = bias[col], b1 = bias[col + 1];
                lo.x = fmaxf(lo.x + b0, 0.f); lo.y = fmaxf(lo.y + b1, 0.f);
                hi.x = fmaxf(hi.x + b0, 0.f); hi.y = fmaxf(hi.y + b1, 0.f);
            }
            if (rbase < nrows)
                *(__half2*)(Ch + (size_t)rbase * FD + col) = __float22half2_rn(lo);
            if (rbase + 8 < nrows)
                *(__half2*)(Ch + (size_t)(rbase + 8) * FD + col) = __float22half2_rn(hi);
        }
    }
}

// ---------------- per-graph mean pool: 1024 thr/graph, 8 row-stripes ------------
__global__ void k_pool(const float* __restrict__ h, const int* __restrict__ bat) {
    int g = blockIdx.x;
    __shared__ int se[2];
    __shared__ float part[7][FD];
    if (threadIdx.x < 2) {
        int target = g + threadIdx.x;
        int lo = 0, hi = NN;
        while (lo < hi) { int m = (lo + hi) >> 1; if (bat[m] < target) lo = m + 1; else hi = m; }
        se[threadIdx.x] = lo;
    }
    __syncthreads();
    int s = se[0], e = se[1];
    int c = threadIdx.x & 127;
    int r0 = threadIdx.x >> 7;
    float acc = 0.f;
    for (int i = s + r0; i < e; i += 8)
        acc += h[(size_t)i * FD + c];
    if (r0 > 0) part[r0 - 1][c] = acc;
    __syncthreads();
    if (r0 == 0) {
        #pragma unroll
        for (int u = 0; u < 7; u++) acc += part[u][c];
        float cnt = (float)((e - s) > 1 ? (e - s) : 1);
        g_pooled[g * FD + c] = acc / cnt;
    }
}

// ---------------- final FC -------------------------------------------------------
__global__ void k_fc(const float* __restrict__ fcW, const float* __restrict__ fcb,
                     float* __restrict__ out) {
    int g = blockIdx.x;
    int c = threadIdx.x;
    float acc = fcb[c];
    #pragma unroll 4
    for (int k = 0; k < FD; k++)
        acc = fmaf(g_pooled[g * FD + k], fcW[k * NC + c], acc);
    out[g * NC + c] = acc;
}

// ---------------- launch ----------------------------------------------------------
extern "C" void kernel_launch(void* const* d_in, const int* in_sizes, int n_in,
                              void* d_out, int out_size) {
    const float* x    = (const float*)d_in[0];
    const int*   ei   = (const int*)d_in[1];
    const int*   bat  = (const int*)d_in[2];
    const float* W1   = (const float*)d_in[3];
    const float* b1   = (const float*)d_in[4];
    const float* W2   = (const float*)d_in[5];
    const float* b2   = (const float*)d_in[6];
    const float* fcW  = (const float*)d_in[7];
    const float* fcb  = (const float*)d_in[8];
    float* out = (float*)d_out;

    int ne = in_sizes[1] / 2;
    const int* src = ei;
    const int* dst = ei + ne;

    float *bufB;
    __half *xh, *aggh, *h1h;
    cudaGetSymbolAddress((void**)&bufB, g_bufB);
    cudaGetSymbolAddress((void**)&xh, g_xh);
    cudaGetSymbolAddress((void**)&aggh, g_aggh);
    cudaGetSymbolAddress((void**)&h1h, g_h1h);

    cudaFuncSetAttribute(k_gemm_f16, cudaFuncAttributeMaxDynamicSharedMemorySize, GEMM_SMEM);

    int tb = 256;
    int gbE   = (ne + tb - 1) / tb;
    int gbAgg = (NN * 32 + tb - 1) / tb;      // 1 warp per node
    int gbGemm = (NN + 127) / 128;

    k_deg_x2h<<<gbE, tb>>>(dst, ne, x);                               // 0
    k_scan<<<NBLK, tb>>>();                                           // 1 (+pad, +cleanup)
    k_scatter<<<gbE, tb>>>(src, dst, ne);                             // 2
    k_agg_pre<<<gbAgg, tb>>>(xh, aggh);                               // 3 <- profiled
    k_gemm_f16<<<gbGemm, tb, GEMM_SMEM>>>(aggh, W1, b1, h1h, NN);     // 4 (bias+relu)
    k_gemm_f16<<<gbGemm, tb, GEMM_SMEM>>>(h1h, W2, nullptr, aggh, NN);// 5 (plain)
    k_agg_post<<<gbAgg, tb>>>(aggh, b2, bufB);                        // 6 (bias+relu)
    k_pool<<<NG, 1024>>>(bufB, bat);                                  // 7
    k_fc<<<NG, NC>>>(fcW, fcb, out);                                  // 8
}